// round 12
// baseline (speedup 1.0000x reference)
#include <cuda_runtime.h>
#include <cuda_fp16.h>
#include <cstdint>

#define IN_DIM   128
#define OUT_DIM  32
#define NCHUNK   8             // 16 inputs per chunk
#define CH_IN    16
#define KSTEPS   9             // per chunk
#define KS_TOT   72            // 1152 / 16
#define ROWPAD   304           // A tile row pitch: 288B data + 16B pad (conflict-free)
#define TPB      256
#define ROWS_CTA 256
#define NCTA     512           // 131072 / 256
#define SMEM_A   (ROWS_CTA * ROWPAD)   // 77,824 B -> dynamic smem

// spline constants: centers start -5/11, step 2/11, spacing 0.4+1e-6
#define KAN_C0   (-5.0f / 11.0f)
#define KAN_IS   (1.0f / (0.4f + 1e-6f))
#define KAN_D1   ((2.0f / 11.0f) * KAN_IS)

// B in fragment order: [kstep][half][lane] -> 16B ( = 4 regs )
__device__ __align__(16) uint4 g_Wf[KS_TOT * 2 * 32];
__device__ __align__(16) float g_bias[OUT_DIM];

// ---------------- helpers ----------------
__device__ __forceinline__ void ldsm4(uint32_t* r, uint32_t a) {
    asm volatile("ldmatrix.sync.aligned.m8n8.x4.shared.b16 {%0,%1,%2,%3}, [%4];"
        : "=r"(r[0]), "=r"(r[1]), "=r"(r[2]), "=r"(r[3]) : "r"(a));
}
__device__ __forceinline__ void mma16816(float* d, const uint32_t* a, const uint32_t* b) {
    asm volatile("mma.sync.aligned.m16n8k16.row.col.f32.f16.f16.f32 "
        "{%0,%1,%2,%3}, {%4,%5,%6,%7}, {%8,%9}, {%0,%1,%2,%3};"
        : "+f"(d[0]), "+f"(d[1]), "+f"(d[2]), "+f"(d[3])
        : "r"(a[0]), "r"(a[1]), "r"(a[2]), "r"(a[3]), "r"(b[0]), "r"(b[1]));
}
__device__ __forceinline__ uint32_t pkhf(float lo, float hi) {   // low half = lo
    uint32_t r;
    asm("cvt.rn.f16x2.f32 %0, %1, %2;" : "=r"(r) : "f"(hi), "f"(lo));
    return r;
}

// ---------------- prep: fold W and emit ldmatrix-equivalent fragments ----------------
// W[k][j] = ew[i][j] * (f==0 ? base_weight[i][j] : coeff[i][j][f-1]),  i=k/9, f=k%9
__device__ __forceinline__ float foldW(int k, int j, const float* coeff,
                                       const float* bw, const float* ew) {
    int i = k / 9, f = k - 9 * i;
    int t = i * OUT_DIM + j;
    float e = ew[t];
    return f == 0 ? e * bw[t] : e * coeff[t * 8 + (f - 1)];
}

__global__ void kan_prep(const float* __restrict__ coeff, const float* __restrict__ bw,
                         const float* __restrict__ bb, const float* __restrict__ ew) {
    int t = blockIdx.x * 256 + threadIdx.x;
    if (t < KS_TOT * 32) {
        int s = t >> 5, l = t & 31;
        uint32_t regs[8];
#pragma unroll
        for (int r = 0; r < 8; ++r) {
            // reg r (ldmatrix.x4.trans equivalent): n-tile r>>1, b-half r&1
            int n  = (r >> 1) * 8 + (l >> 2);
            int kk = 16 * s + 2 * (l & 3) + 8 * (r & 1);
            float lo = foldW(kk,     n, coeff, bw, ew);
            float hi = foldW(kk + 1, n, coeff, bw, ew);
            regs[r] = pkhf(lo, hi);
        }
        g_Wf[(s * 2 + 0) * 32 + l] = make_uint4(regs[0], regs[1], regs[2], regs[3]); // b01
        g_Wf[(s * 2 + 1) * 32 + l] = make_uint4(regs[4], regs[5], regs[6], regs[7]); // b23
    }
    if (blockIdx.x == 0 && threadIdx.x < OUT_DIM) {
        int j = threadIdx.x;
        float s = 0.0f;
        for (int i = 0; i < IN_DIM; ++i) s += ew[i * OUT_DIM + j] * bb[i * OUT_DIM + j];
        g_bias[j] = s;
    }
}

// ---------------- feature math ----------------
__device__ __forceinline__ void feats(float xq, float* f) {
    const float QC = __expf(-KAN_D1 * KAN_D1);
    const float MB = -0.5f * KAN_D1 * KAN_D1;
    float e = __expf(-xq);
    f[0] = __fdividef(xq, 1.0f + e);                 // silu
    float z0 = (xq - KAN_C0) * KAN_IS;
    float b = __expf(-0.5f * z0 * z0);
    float m = __expf(fmaf(z0, KAN_D1, MB));
    f[1] = b;
#pragma unroll
    for (int k = 2; k <= 8; ++k) { b *= m; m *= QC; f[k] = b; }
}

// one group: 8 inputs -> 72 fp16 slots -> 36 words -> 9 uint4 STS
__device__ __forceinline__ void feat_group(const float* xq, uint8_t* dst) {
    uint32_t w[36];
    float carry = 0.0f;
#pragma unroll
    for (int q = 0; q < 8; ++q) {
        float f[9];
        feats(xq[q], f);
#pragma unroll
        for (int t = 0; t < 9; ++t) {
            int idx = 9 * q + t;
            if (idx & 1) w[idx >> 1] = pkhf(carry, f[t]);
            else         carry = f[t];
        }
    }
    uint4* d4 = (uint4*)dst;
#pragma unroll
    for (int i = 0; i < 9; ++i)
        d4[i] = make_uint4(w[4 * i], w[4 * i + 1], w[4 * i + 2], w[4 * i + 3]);
}

// ---------------- main ----------------
extern __shared__ uint8_t smA[];

__global__ __launch_bounds__(TPB, 2)
void kan_main(const float* __restrict__ x, float* __restrict__ out) {
    const int tid  = threadIdx.x;
    const int wid  = tid >> 5;              // 0..7, one 32-row m-tile each
    const int lane = tid & 31;
    const int g    = lane >> 2;
    const int tig  = lane & 3;

    uint32_t a_b;
    asm("{ .reg .u64 t; cvta.to.shared.u64 t, %1; cvt.u32.u64 %0, t; }"
        : "=r"(a_b) : "l"((const void*)smA));

    const int rowBase = blockIdx.x * ROWS_CTA;
    const float* __restrict__ xrow = x + (size_t)(rowBase + tid) * IN_DIM;

    float2 bias[4];
#pragma unroll
    for (int j = 0; j < 4; ++j) bias[j] = *(const float2*)(g_bias + j * 8 + tig * 2);

    float acc[2][4][4];
#pragma unroll
    for (int t = 0; t < 2; ++t)
#pragma unroll
        for (int j = 0; j < 4; ++j)
#pragma unroll
            for (int r = 0; r < 4; ++r) acc[t][j][r] = 0.0f;

    // ---- prologue: features(0) -> A tile ----
    {
        float xq[8];
#pragma unroll
        for (int p = 0; p < 2; ++p) {
            *(float4*)(xq)     = *(const float4*)(xrow + p * 8);
            *(float4*)(xq + 4) = *(const float4*)(xrow + p * 8 + 4);
            feat_group(xq, smA + (size_t)tid * ROWPAD + p * 144);
        }
    }

#pragma unroll 1
    for (int c = 0; c < NCHUNK; ++c) {
        __syncthreads();                             // A(c) visible to all warps

        // prefetch next chunk's x early (long latency tolerated)
        float xq[8];
        if (c + 1 < NCHUNK) {
            *(float4*)(xq)     = *(const float4*)(xrow + (c + 1) * CH_IN);
            *(float4*)(xq + 4) = *(const float4*)(xrow + (c + 1) * CH_IN + 4);
        }

        // ---- MMA(c): B frags via LDG (shared by all 8 warps), A via ldmatrix ----
        const uint4* __restrict__ wf = g_Wf + (size_t)(c * KSTEPS) * 64 + lane;
        const uint32_t aW = a_b + (uint32_t)(wid * 32) * ROWPAD;
#pragma unroll
        for (int s = 0; s < KSTEPS; ++s) {
            uint4 v01 = __ldg(wf + s * 64);
            uint4 v23 = __ldg(wf + s * 64 + 32);
            uint32_t b01[4] = {v01.x, v01.y, v01.z, v01.w};
            uint32_t b23[4] = {v23.x, v23.y, v23.z, v23.w};
            uint32_t a0[4], a1[4];
            uint32_t arow = aW + (uint32_t)(lane & 15) * ROWPAD + s * 32 + (lane >> 4) * 16;
            ldsm4(a0, arow);
            ldsm4(a1, arow + 16 * ROWPAD);
            mma16816(acc[0][0], a0, b01 + 0); mma16816(acc[0][1], a0, b01 + 2);
            mma16816(acc[0][2], a0, b23 + 0); mma16816(acc[0][3], a0, b23 + 2);
            mma16816(acc[1][0], a1, b01 + 0); mma16816(acc[1][1], a1, b01 + 2);
            mma16816(acc[1][2], a1, b23 + 0); mma16816(acc[1][3], a1, b23 + 2);
        }

        __syncthreads();                             // all ldsm reads of A(c) done

        // ---- features(c+1) -> A tile (overlaps HMMA drain) ----
        if (c + 1 < NCHUNK) {
            feat_group(xq, smA + (size_t)tid * ROWPAD);
            float xq2[8];
            *(float4*)(xq2)     = *(const float4*)(xrow + (c + 1) * CH_IN + 8);
            *(float4*)(xq2 + 4) = *(const float4*)(xrow + (c + 1) * CH_IN + 12);
            feat_group(xq2, smA + (size_t)tid * ROWPAD + 144);
        }
    }

    // epilogue: bias + store (D frag: d0,d1 -> row g; d2,d3 -> row g+8)
#pragma unroll
    for (int t = 0; t < 2; ++t) {
        int r0 = rowBase + wid * 32 + t * 16 + g;
#pragma unroll
        for (int j = 0; j < 4; ++j) {
            float2 v0 = make_float2(acc[t][j][0] + bias[j].x, acc[t][j][1] + bias[j].y);
            float2 v1 = make_float2(acc[t][j][2] + bias[j].x, acc[t][j][3] + bias[j].y);
            *(float2*)(out + (size_t)r0 * OUT_DIM + j * 8 + tig * 2)       = v0;
            *(float2*)(out + (size_t)(r0 + 8) * OUT_DIM + j * 8 + tig * 2) = v1;
        }
    }
}

// ---------------- launch ----------------
extern "C" void kernel_launch(void* const* d_in, const int* in_sizes, int n_in,
                              void* d_out, int out_size) {
    (void)in_sizes; (void)n_in; (void)out_size;
    const float* x     = (const float*)d_in[0];
    const float* coeff = (const float*)d_in[1];
    const float* bw    = (const float*)d_in[2];
    const float* bb    = (const float*)d_in[3];
    const float* ew    = (const float*)d_in[4];
    float* out = (float*)d_out;

    cudaFuncSetAttribute(kan_main, cudaFuncAttributeMaxDynamicSharedMemorySize, SMEM_A);

    kan_prep<<<9, 256>>>(coeff, bw, bb, ew);
    kan_main<<<NCTA, TPB, SMEM_A>>>(x, out);
}

// round 13
// speedup vs baseline: 1.0406x; 1.0406x over previous
#include <cuda_runtime.h>
#include <cuda_fp16.h>
#include <cstdint>

#define IN_DIM   128
#define OUT_DIM  32
#define NCHUNK   8             // 16 inputs per chunk
#define CH_IN    16
#define KSTEPS   9             // per chunk
#define KS_TOT   72            // 1152 / 16
#define ROWPAD   304           // A tile row pitch: 288B data + 16B pad (conflict-free)
#define TPB      128
#define NCTA     1024          // 131072 rows / 128

// spline constants: centers start -5/11, step 2/11, spacing 0.4+1e-6
#define KAN_C0   (-5.0f / 11.0f)
#define KAN_IS   (1.0f / (0.4f + 1e-6f))
#define KAN_D1   ((2.0f / 11.0f) * KAN_IS)

// B in fragment order: [kstep][half][lane] -> 16B ( = 4 regs )
__device__ __align__(16) uint4 g_Wf[KS_TOT * 2 * 32];
__device__ __align__(16) float g_bias[OUT_DIM];

// ---------------- helpers ----------------
__device__ __forceinline__ void ldsm4(uint32_t* r, uint32_t a) {
    asm volatile("ldmatrix.sync.aligned.m8n8.x4.shared.b16 {%0,%1,%2,%3}, [%4];"
        : "=r"(r[0]), "=r"(r[1]), "=r"(r[2]), "=r"(r[3]) : "r"(a));
}
__device__ __forceinline__ void mma16816(float* d, const uint32_t* a, const uint32_t* b) {
    asm volatile("mma.sync.aligned.m16n8k16.row.col.f32.f16.f16.f32 "
        "{%0,%1,%2,%3}, {%4,%5,%6,%7}, {%8,%9}, {%0,%1,%2,%3};"
        : "+f"(d[0]), "+f"(d[1]), "+f"(d[2]), "+f"(d[3])
        : "r"(a[0]), "r"(a[1]), "r"(a[2]), "r"(a[3]), "r"(b[0]), "r"(b[1]));
}
__device__ __forceinline__ uint32_t pkhf(float lo, float hi) {   // low half = lo
    uint32_t r;
    asm("cvt.rn.f16x2.f32 %0, %1, %2;" : "=r"(r) : "f"(hi), "f"(lo));
    return r;
}

// ---------------- prep: fold W and emit ldmatrix-equivalent fragments ----------------
// W[k][j] = ew[i][j] * (f==0 ? base_weight[i][j] : coeff[i][j][f-1]),  i=k/9, f=k%9
__device__ __forceinline__ float foldW(int k, int j, const float* coeff,
                                       const float* bw, const float* ew) {
    int i = k / 9, f = k - 9 * i;
    int t = i * OUT_DIM + j;
    float e = ew[t];
    return f == 0 ? e * bw[t] : e * coeff[t * 8 + (f - 1)];
}

__global__ void kan_prep(const float* __restrict__ coeff, const float* __restrict__ bw,
                         const float* __restrict__ bb, const float* __restrict__ ew) {
    int t = blockIdx.x * 256 + threadIdx.x;
    if (t < KS_TOT * 32) {
        int s = t >> 5, l = t & 31;
        uint32_t regs[8];
#pragma unroll
        for (int r = 0; r < 8; ++r) {
            // reg r (ldmatrix.x4.trans equivalent): n-tile r>>1, b-half r&1
            int n  = (r >> 1) * 8 + (l >> 2);
            int kk = 16 * s + 2 * (l & 3) + 8 * (r & 1);
            float lo = foldW(kk,     n, coeff, bw, ew);
            float hi = foldW(kk + 1, n, coeff, bw, ew);
            regs[r] = pkhf(lo, hi);
        }
        g_Wf[(s * 2 + 0) * 32 + l] = make_uint4(regs[0], regs[1], regs[2], regs[3]); // b01
        g_Wf[(s * 2 + 1) * 32 + l] = make_uint4(regs[4], regs[5], regs[6], regs[7]); // b23
    }
    if (blockIdx.x == 0 && threadIdx.x < OUT_DIM) {
        int j = threadIdx.x;
        float s = 0.0f;
        for (int i = 0; i < IN_DIM; ++i) s += ew[i * OUT_DIM + j] * bb[i * OUT_DIM + j];
        g_bias[j] = s;
    }
}

// ---------------- feature math ----------------
__device__ __forceinline__ void feats(float xq, float* f) {
    const float QC = __expf(-KAN_D1 * KAN_D1);
    const float MB = -0.5f * KAN_D1 * KAN_D1;
    float e = __expf(-xq);
    f[0] = __fdividef(xq, 1.0f + e);                 // silu
    float z0 = (xq - KAN_C0) * KAN_IS;
    float b = __expf(-0.5f * z0 * z0);
    float m = __expf(fmaf(z0, KAN_D1, MB));
    f[1] = b;
#pragma unroll
    for (int k = 2; k <= 8; ++k) { b *= m; m *= QC; f[k] = b; }
}

// one group: 8 inputs -> 72 fp16 slots -> 36 words -> 9 uint4 STS
__device__ __forceinline__ void feat_group(const float* xq, uint8_t* dst) {
    uint32_t w[36];
    float carry = 0.0f;
#pragma unroll
    for (int q = 0; q < 8; ++q) {
        float f[9];
        feats(xq[q], f);
#pragma unroll
        for (int t = 0; t < 9; ++t) {
            int idx = 9 * q + t;
            if (idx & 1) w[idx >> 1] = pkhf(carry, f[t]);
            else         carry = f[t];
        }
    }
    uint4* d4 = (uint4*)dst;
#pragma unroll
    for (int i = 0; i < 9; ++i)
        d4[i] = make_uint4(w[4 * i], w[4 * i + 1], w[4 * i + 2], w[4 * i + 3]);
}

// ---------------- main: fully warp-independent pipelines (no block barriers) ----------------
// Warp w owns rows [32w, 32w+32): its threads compute features for exactly those
// rows into its private A slab, and its ldmatrix reads only that slab. B is
// read-only, accumulators are registers -> __syncwarp() is the only sync needed.
__global__ __launch_bounds__(TPB, 4)
void kan_main(const float* __restrict__ x, float* __restrict__ out) {
    __shared__ __align__(16) uint8_t smA[TPB * ROWPAD];   // 38,912 B; per-warp slabs

    const int tid  = threadIdx.x;
    const int wid  = tid >> 5;
    const int lane = tid & 31;
    const int g    = lane >> 2;
    const int tig  = lane & 3;

    uint32_t a_b;
    asm("{ .reg .u64 t; cvta.to.shared.u64 t, %1; cvt.u32.u64 %0, t; }"
        : "=r"(a_b) : "l"((const void*)smA));

    const int rowBase = blockIdx.x * TPB;
    const float* __restrict__ xrow = x + (size_t)(rowBase + tid) * IN_DIM;

    float2 bias[4];
#pragma unroll
    for (int j = 0; j < 4; ++j) bias[j] = *(const float2*)(g_bias + j * 8 + tig * 2);

    float acc[2][4][4];
#pragma unroll
    for (int t = 0; t < 2; ++t)
#pragma unroll
        for (int j = 0; j < 4; ++j)
#pragma unroll
            for (int r = 0; r < 4; ++r) acc[t][j][r] = 0.0f;

    // ---- prologue: features(0) -> own slab ----
    {
        float xq[8];
#pragma unroll
        for (int p = 0; p < 2; ++p) {
            *(float4*)(xq)     = *(const float4*)(xrow + p * 8);
            *(float4*)(xq + 4) = *(const float4*)(xrow + p * 8 + 4);
            feat_group(xq, smA + (size_t)tid * ROWPAD + p * 144);
        }
    }

#pragma unroll 1
    for (int c = 0; c < NCHUNK; ++c) {
        __syncwarp();                                // own warp's A(c) STS visible

        // prefetch next chunk's x early (long latency tolerated)
        float xq[8];
        if (c + 1 < NCHUNK) {
            *(float4*)(xq)     = *(const float4*)(xrow + (c + 1) * CH_IN);
            *(float4*)(xq + 4) = *(const float4*)(xrow + (c + 1) * CH_IN + 4);
        }

        // ---- MMA(c): B frags via LDG (L1/L2-hot), A via ldmatrix from own slab ----
        const uint4* __restrict__ wf = g_Wf + (size_t)(c * KSTEPS) * 64 + lane;
        const uint32_t aW = a_b + (uint32_t)(wid * 32) * ROWPAD;
#pragma unroll
        for (int s = 0; s < KSTEPS; ++s) {
            uint4 v01 = __ldg(wf + s * 64);
            uint4 v23 = __ldg(wf + s * 64 + 32);
            uint32_t b01[4] = {v01.x, v01.y, v01.z, v01.w};
            uint32_t b23[4] = {v23.x, v23.y, v23.z, v23.w};
            uint32_t a0[4], a1[4];
            uint32_t arow = aW + (uint32_t)(lane & 15) * ROWPAD + s * 32 + (lane >> 4) * 16;
            ldsm4(a0, arow);
            ldsm4(a1, arow + 16 * ROWPAD);
            mma16816(acc[0][0], a0, b01 + 0); mma16816(acc[0][1], a0, b01 + 2);
            mma16816(acc[0][2], a0, b23 + 0); mma16816(acc[0][3], a0, b23 + 2);
            mma16816(acc[1][0], a1, b01 + 0); mma16816(acc[1][1], a1, b01 + 2);
            mma16816(acc[1][2], a1, b23 + 0); mma16816(acc[1][3], a1, b23 + 2);
        }

        __syncwarp();                                // own warp's ldsm reads of A(c) done

        // ---- features(c+1) -> own slab (other warps keep issuing HMMA meanwhile) ----
        if (c + 1 < NCHUNK) {
            feat_group(xq, smA + (size_t)tid * ROWPAD);
            float xq2[8];
            *(float4*)(xq2)     = *(const float4*)(xrow + (c + 1) * CH_IN + 8);
            *(float4*)(xq2 + 4) = *(const float4*)(xrow + (c + 1) * CH_IN + 12);
            feat_group(xq2, smA + (size_t)tid * ROWPAD + 144);
        }
    }

    // epilogue: bias + store (D frag: d0,d1 -> row g; d2,d3 -> row g+8)
#pragma unroll
    for (int t = 0; t < 2; ++t) {
        int r0 = rowBase + wid * 32 + t * 16 + g;
#pragma unroll
        for (int j = 0; j < 4; ++j) {
            float2 v0 = make_float2(acc[t][j][0] + bias[j].x, acc[t][j][1] + bias[j].y);
            float2 v1 = make_float2(acc[t][j][2] + bias[j].x, acc[t][j][3] + bias[j].y);
            *(float2*)(out + (size_t)r0 * OUT_DIM + j * 8 + tig * 2)       = v0;
            *(float2*)(out + (size_t)(r0 + 8) * OUT_DIM + j * 8 + tig * 2) = v1;
        }
    }
}

// ---------------- launch ----------------
extern "C" void kernel_launch(void* const* d_in, const int* in_sizes, int n_in,
                              void* d_out, int out_size) {
    (void)in_sizes; (void)n_in; (void)out_size;
    const float* x     = (const float*)d_in[0];
    const float* coeff = (const float*)d_in[1];
    const float* bw    = (const float*)d_in[2];
    const float* bb    = (const float*)d_in[3];
    const float* ew    = (const float*)d_in[4];
    float* out = (float*)d_out;

    kan_prep<<<9, 256>>>(coeff, bw, bb, ew);
    kan_main<<<NCTA, TPB>>>(x, out);
}

// round 14
// speedup vs baseline: 1.0417x; 1.0010x over previous
#include <cuda_runtime.h>
#include <cuda_fp16.h>
#include <cstdint>

#define IN_DIM   128
#define OUT_DIM  32
#define NCHUNK   8             // 16 inputs per chunk
#define CH_IN    16
#define KSTEPS   9             // per chunk
#define KS_TOT   72            // 1152 / 16
#define ROWPAD   304           // A tile row pitch: 288B data + 16B pad (conflict-free)
#define TPB      128
#define NCTA     1024          // 131072 rows / 128

// spline constants: centers start -5/11, step 2/11, spacing 0.4+1e-6
#define KAN_C0   (-5.0f / 11.0f)
#define KAN_IS   (1.0f / (0.4f + 1e-6f))
#define KAN_D1   ((2.0f / 11.0f) * KAN_IS)
#define L2E      1.44269504088896340736f
#define C_ZA     (KAN_IS)                       // z = x*ZA + ZB
#define C_ZB     (-(KAN_C0) * (KAN_IS))
#define C_NH     (-0.5f * L2E)                  // barg = z^2 * NH
#define C_MD     ((KAN_D1) * L2E)               // marg = z*MD + MC
#define C_MC     (-0.5f * (KAN_D1) * (KAN_D1) * L2E)
#define C_NE     (-L2E)                         // earg = x * NE
#define C_QA     (-(KAN_D1) * (KAN_D1) * L2E)   // qc = ex2(QA)

// B in fragment order: [kstep][half][lane] -> 16B ( = 4 regs )
__device__ __align__(16) uint4 g_Wf[KS_TOT * 2 * 32];
__device__ __align__(16) float g_bias[OUT_DIM];

typedef unsigned long long u64;

// ---------------- helpers ----------------
__device__ __forceinline__ void ldsm4(uint32_t* r, uint32_t a) {
    asm volatile("ldmatrix.sync.aligned.m8n8.x4.shared.b16 {%0,%1,%2,%3}, [%4];"
        : "=r"(r[0]), "=r"(r[1]), "=r"(r[2]), "=r"(r[3]) : "r"(a));
}
__device__ __forceinline__ void mma16816(float* d, const uint32_t* a, const uint32_t* b) {
    asm volatile("mma.sync.aligned.m16n8k16.row.col.f32.f16.f16.f32 "
        "{%0,%1,%2,%3}, {%4,%5,%6,%7}, {%8,%9}, {%0,%1,%2,%3};"
        : "+f"(d[0]), "+f"(d[1]), "+f"(d[2]), "+f"(d[3])
        : "r"(a[0]), "r"(a[1]), "r"(a[2]), "r"(a[3]), "r"(b[0]), "r"(b[1]));
}
__device__ __forceinline__ uint32_t pkhf(float lo, float hi) {   // low half = lo
    uint32_t r;
    asm("cvt.rn.f16x2.f32 %0, %1, %2;" : "=r"(r) : "f"(hi), "f"(lo));
    return r;
}
// packed f32x2
__device__ __forceinline__ u64 pk2(float a, float b) {
    u64 r; asm("mov.b64 %0, {%1, %2};" : "=l"(r) : "f"(a), "f"(b)); return r;
}
__device__ __forceinline__ void up2(u64 v, float& a, float& b) {
    asm("mov.b64 {%0, %1}, %2;" : "=f"(a), "=f"(b) : "l"(v));
}
__device__ __forceinline__ u64 mul2(u64 a, u64 b) {
    u64 d; asm("mul.rn.f32x2 %0, %1, %2;" : "=l"(d) : "l"(a), "l"(b)); return d;
}
__device__ __forceinline__ u64 fma2(u64 a, u64 b, u64 c) {
    u64 d; asm("fma.rn.f32x2 %0, %1, %2, %3;" : "=l"(d) : "l"(a), "l"(b), "l"(c)); return d;
}
__device__ __forceinline__ float ex2f(float x) {
    float r; asm("ex2.approx.f32 %0, %1;" : "=f"(r) : "f"(x)); return r;
}
__device__ __forceinline__ float rcpf(float x) {
    float r; asm("rcp.approx.f32 %0, %1;" : "=f"(r) : "f"(x)); return r;
}

// ---------------- prep: fold W and emit ldmatrix-equivalent fragments ----------------
__device__ __forceinline__ float foldW(int k, int j, const float* coeff,
                                       const float* bw, const float* ew) {
    int i = k / 9, f = k - 9 * i;
    int t = i * OUT_DIM + j;
    float e = ew[t];
    return f == 0 ? e * bw[t] : e * coeff[t * 8 + (f - 1)];
}

__global__ void kan_prep(const float* __restrict__ coeff, const float* __restrict__ bw,
                         const float* __restrict__ bb, const float* __restrict__ ew) {
    int t = blockIdx.x * 256 + threadIdx.x;
    if (t < KS_TOT * 32) {
        int s = t >> 5, l = t & 31;
        uint32_t regs[8];
#pragma unroll
        for (int r = 0; r < 8; ++r) {
            int n  = (r >> 1) * 8 + (l >> 2);
            int kk = 16 * s + 2 * (l & 3) + 8 * (r & 1);
            float lo = foldW(kk,     n, coeff, bw, ew);
            float hi = foldW(kk + 1, n, coeff, bw, ew);
            regs[r] = pkhf(lo, hi);
        }
        g_Wf[(s * 2 + 0) * 32 + l] = make_uint4(regs[0], regs[1], regs[2], regs[3]); // b01
        g_Wf[(s * 2 + 1) * 32 + l] = make_uint4(regs[4], regs[5], regs[6], regs[7]); // b23
    }
    if (blockIdx.x == 0 && threadIdx.x < OUT_DIM) {
        int j = threadIdx.x;
        float s = 0.0f;
        for (int i = 0; i < IN_DIM; ++i) s += ew[i * OUT_DIM + j] * bb[i * OUT_DIM + j];
        g_bias[j] = s;
    }
}

// ---------------- feature math: f32x2-packed pair path ----------------
struct FC { u64 za, zb, qc; };

__device__ __forceinline__ void feat_pair(const FC& C, float xa, float xb, uint32_t* w) {
    u64 x2 = pk2(xa, xb);
    u64 z2 = fma2(x2, C.za, C.zb);                 // z = x*IS - C0*IS
    u64 zz2 = mul2(z2, z2);
    float za_, zb_, zza, zzb;
    up2(z2, za_, zb_); up2(zz2, zza, zzb);
    float ba = ex2f(zza * C_NH);                   // b = 2^(NH*z^2)
    float bb_ = ex2f(zzb * C_NH);
    float ma = ex2f(fmaf(za_, C_MD, C_MC));        // m = 2^(z*MD+MC)
    float mb = ex2f(fmaf(zb_, C_MD, C_MC));
    float ea = ex2f(xa * C_NE);                    // e = 2^(-x*L2E) = exp(-x)
    float eb = ex2f(xb * C_NE);
    u64 r2 = pk2(rcpf(ea + 1.0f), rcpf(eb + 1.0f));
    u64 s2 = mul2(x2, r2);                         // silu = x * rcp(1+e)
    float fa[9], fb[9];
    up2(s2, fa[0], fb[0]);
    fa[1] = ba; fb[1] = bb_;
    u64 b2 = pk2(ba, bb_), m2 = pk2(ma, mb);
#pragma unroll
    for (int k = 2; k <= 8; ++k) {
        b2 = mul2(b2, m2);
        m2 = mul2(m2, C.qc);
        up2(b2, fa[k], fb[k]);
    }
    w[0] = pkhf(fa[0], fa[1]); w[1] = pkhf(fa[2], fa[3]);
    w[2] = pkhf(fa[4], fa[5]); w[3] = pkhf(fa[6], fa[7]);
    w[4] = pkhf(fa[8], fb[0]); w[5] = pkhf(fb[1], fb[2]);
    w[6] = pkhf(fb[3], fb[4]); w[7] = pkhf(fb[5], fb[6]);
    w[8] = pkhf(fb[7], fb[8]);
}

// 8 inputs -> 36 words -> 9 uint4 STS
__device__ __forceinline__ void feat_group(const FC& C, const float* xq, uint8_t* dst) {
    uint32_t w[36];
#pragma unroll
    for (int p = 0; p < 4; ++p)
        feat_pair(C, xq[2 * p], xq[2 * p + 1], w + 9 * p);
    uint4* d4 = (uint4*)dst;
#pragma unroll
    for (int i = 0; i < 9; ++i)
        d4[i] = make_uint4(w[4 * i], w[4 * i + 1], w[4 * i + 2], w[4 * i + 3]);
}

// ---------------- main: warp-independent pipelines + per-warp chunk rotation ----------------
__global__ __launch_bounds__(TPB, 4)
void kan_main(const float* __restrict__ x, float* __restrict__ out) {
    __shared__ __align__(16) uint8_t smA[TPB * ROWPAD];   // per-warp private slabs

    const int tid  = threadIdx.x;
    const int wid  = tid >> 5;
    const int lane = tid & 31;
    const int g    = lane >> 2;
    const int tig  = lane & 3;

    uint32_t a_b;
    asm("{ .reg .u64 t; cvta.to.shared.u64 t, %1; cvt.u32.u64 %0, t; }"
        : "=r"(a_b) : "l"((const void*)smA));

    const int rowBase = blockIdx.x * TPB;
    const float* __restrict__ xrow = x + (size_t)(rowBase + tid) * IN_DIM;

    FC C;
    C.za = pk2(C_ZA, C_ZA);
    C.zb = pk2(C_ZB, C_ZB);
    {
        float qc = ex2f(C_QA);
        C.qc = pk2(qc, qc);
    }

    float2 bias[4];
#pragma unroll
    for (int j = 0; j < 4; ++j) bias[j] = *(const float2*)(g_bias + j * 8 + tig * 2);

    float acc[2][4][4];
#pragma unroll
    for (int t = 0; t < 2; ++t)
#pragma unroll
        for (int j = 0; j < 4; ++j)
#pragma unroll
            for (int r = 0; r < 4; ++r) acc[t][j][r] = 0.0f;

    const int c0 = (wid * 2) & 7;        // per-warp rotated chunk order

    // ---- prologue: features(chunk c0) -> own slab ----
    {
        float xq[8];
#pragma unroll
        for (int p = 0; p < 2; ++p) {
            const float* xs = xrow + c0 * CH_IN + p * 8;
            *(float4*)(xq)     = *(const float4*)(xs);
            *(float4*)(xq + 4) = *(const float4*)(xs + 4);
            feat_group(C, xq, smA + (size_t)tid * ROWPAD + p * 144);
        }
    }

#pragma unroll 1
    for (int c = 0; c < NCHUNK; ++c) {
        const int cr = (c0 + c) & 7;                 // this warp's chunk this iter
        const int cn = (c0 + c + 1) & 7;             // next chunk
        __syncwarp();                                // own warp's A STS visible

        float xq[8];
        if (c + 1 < NCHUNK) {
            const float* xs = xrow + cn * CH_IN;
            *(float4*)(xq)     = *(const float4*)(xs);
            *(float4*)(xq + 4) = *(const float4*)(xs + 4);
        }

        // ---- MMA(cr): B frags via LDG (L1/L2-hot), A via ldmatrix from own slab ----
        const uint4* __restrict__ wf = g_Wf + (size_t)(cr * KSTEPS) * 64 + lane;
        const uint32_t aW = a_b + (uint32_t)(wid * 32) * ROWPAD;
#pragma unroll
        for (int s = 0; s < KSTEPS; ++s) {
            uint4 v01 = __ldg(wf + s * 64);
            uint4 v23 = __ldg(wf + s * 64 + 32);
            uint32_t b01[4] = {v01.x, v01.y, v01.z, v01.w};
            uint32_t b23[4] = {v23.x, v23.y, v23.z, v23.w};
            uint32_t a0[4], a1[4];
            uint32_t arow = aW + (uint32_t)(lane & 15) * ROWPAD + s * 32 + (lane >> 4) * 16;
            ldsm4(a0, arow);
            ldsm4(a1, arow + 16 * ROWPAD);
            mma16816(acc[0][0], a0, b01 + 0); mma16816(acc[0][1], a0, b01 + 2);
            mma16816(acc[0][2], a0, b23 + 0); mma16816(acc[0][3], a0, b23 + 2);
            mma16816(acc[1][0], a1, b01 + 0); mma16816(acc[1][1], a1, b01 + 2);
            mma16816(acc[1][2], a1, b23 + 0); mma16816(acc[1][3], a1, b23 + 2);
        }

        __syncwarp();                                // own warp's ldsm reads done

        // ---- features(cn) -> own slab (other warps keep issuing HMMA meanwhile) ----
        if (c + 1 < NCHUNK) {
            feat_group(C, xq, smA + (size_t)tid * ROWPAD);
            float xq2[8];
            const float* xs = xrow + cn * CH_IN + 8;
            *(float4*)(xq2)     = *(const float4*)(xs);
            *(float4*)(xq2 + 4) = *(const float4*)(xs + 4);
            feat_group(C, xq2, smA + (size_t)tid * ROWPAD + 144);
        }
    }

    // epilogue: bias + store (D frag: d0,d1 -> row g; d2,d3 -> row g+8)
#pragma unroll
    for (int t = 0; t < 2; ++t) {
        int r0 = rowBase + wid * 32 + t * 16 + g;
#pragma unroll
        for (int j = 0; j < 4; ++j) {
            float2 v0 = make_float2(acc[t][j][0] + bias[j].x, acc[t][j][1] + bias[j].y);
            float2 v1 = make_float2(acc[t][j][2] + bias[j].x, acc[t][j][3] + bias[j].y);
            *(float2*)(out + (size_t)r0 * OUT_DIM + j * 8 + tig * 2)       = v0;
            *(float2*)(out + (size_t)(r0 + 8) * OUT_DIM + j * 8 + tig * 2) = v1;
        }
    }
}

// ---------------- launch ----------------
extern "C" void kernel_launch(void* const* d_in, const int* in_sizes, int n_in,
                              void* d_out, int out_size) {
    (void)in_sizes; (void)n_in; (void)out_size;
    const float* x     = (const float*)d_in[0];
    const float* coeff = (const float*)d_in[1];
    const float* bw    = (const float*)d_in[2];
    const float* bb    = (const float*)d_in[3];
    const float* ew    = (const float*)d_in[4];
    float* out = (float*)d_out;

    kan_prep<<<9, 256>>>(coeff, bw, bb, ew);
    kan_main<<<NCTA, TPB>>>(x, out);
}